// round 2
// baseline (speedup 1.0000x reference)
#include <cuda_runtime.h>
#include <math.h>

#define NTEST  4096
#define NTRAIN 8192
#define KDIM   1024

#define BM  128
#define BN  128
#define BK  8
#define BMP 132   // padded row to kill smem store bank conflicts

__device__ float g_inv_test[NTEST];
__device__ float g_inv_train[NTRAIN];
__device__ float g_labf[NTRAIN];
__device__ float g_S[NTEST * 2];

// ---------------------------------------------------------------------------
// Label prep: detect int64 vs int32 storage (JAX may silently downcast) and
// convert to float 0/1. Single block.
// ---------------------------------------------------------------------------
__global__ void label_kernel(const int* __restrict__ l32) {
    __shared__ int is64;
    if (threadIdx.x == 0) is64 = 1;
    __syncthreads();
    // int64 little-endian view: odd int32 slots are high words == 0.
    // int32 view: odd slots are labels, ~half are 1.
    for (int i = threadIdx.x; i < NTRAIN / 2; i += blockDim.x) {
        if (l32[2 * i + 1] != 0) is64 = 0;
    }
    __syncthreads();
    const bool b64 = (is64 != 0);
    for (int i = threadIdx.x; i < NTRAIN; i += blockDim.x) {
        int v = b64 ? l32[2 * i] : l32[i];
        g_labf[i] = (float)v;
    }
}

// ---------------------------------------------------------------------------
// Row inverse L2 norms for test (rows [0,NTEST)) and train (rest).
// ---------------------------------------------------------------------------
__global__ void norm_kernel(const float* __restrict__ test,
                            const float* __restrict__ train) {
    int row = blockIdx.x;
    const float* src;
    float* dst;
    if (row < NTEST) { src = test  + (size_t)row * KDIM;          dst = &g_inv_test[row]; }
    else             { src = train + (size_t)(row - NTEST) * KDIM; dst = &g_inv_train[row - NTEST]; }

    float s = 0.f;
    const float4* s4 = (const float4*)src;
    for (int i = threadIdx.x; i < KDIM / 4; i += blockDim.x) {
        float4 v = s4[i];
        s += v.x * v.x + v.y * v.y + v.z * v.z + v.w * v.w;
    }
    #pragma unroll
    for (int off = 16; off; off >>= 1) s += __shfl_down_sync(0xFFFFFFFFu, s, off);
    __shared__ float red[8];
    int lane = threadIdx.x & 31, w = threadIdx.x >> 5;
    if (lane == 0) red[w] = s;
    __syncthreads();
    if (threadIdx.x == 0) {
        float t = 0.f;
        int nw = blockDim.x >> 5;
        for (int i = 0; i < nw; i++) t += red[i];
        *dst = 1.0f / sqrtf(t);
    }
}

__global__ void zero_kernel() {
    int i = blockIdx.x * blockDim.x + threadIdx.x;
    if (i < NTEST * 2) g_S[i] = 0.f;
}

// ---------------------------------------------------------------------------
// Fused GEMM + PNN epilogue.
// Block computes a 128(test) x 128(train) dot tile; epilogue converts each dot
// to the Gauss kernel value and reduces per-class sums for each test row.
// ---------------------------------------------------------------------------
__global__ __launch_bounds__(256, 2)
void pnn_gemm(const float* __restrict__ A,   // test  [NTEST, K]
              const float* __restrict__ B) { // train [NTRAIN, K]
    __shared__ float As[2][BK][BMP];
    __shared__ float Bs[2][BK][BMP];
    __shared__ float labf[BN];

    const int tid = threadIdx.x;
    const int tm = tid & 15, tp = tid >> 4;
    const int prow0 = blockIdx.y * BM;
    const int mcol0 = blockIdx.x * BN;

    for (int i = tid; i < BN; i += 256) labf[i] = g_labf[mcol0 + i];

    const int arow = tid >> 1;
    const int akq  = (tid & 1) * 4;
    const float* Ag = A + (size_t)(prow0 + arow) * KDIM + akq;
    const float* Bg = B + (size_t)(mcol0 + arow) * KDIM + akq;

    float acc[8][8];
    #pragma unroll
    for (int i = 0; i < 8; i++)
        #pragma unroll
        for (int j = 0; j < 8; j++) acc[i][j] = 0.f;

    float4 ra = *(const float4*)Ag;
    float4 rb = *(const float4*)Bg;
    As[0][akq + 0][arow] = ra.x; As[0][akq + 1][arow] = ra.y;
    As[0][akq + 2][arow] = ra.z; As[0][akq + 3][arow] = ra.w;
    Bs[0][akq + 0][arow] = rb.x; Bs[0][akq + 1][arow] = rb.y;
    Bs[0][akq + 2][arow] = rb.z; Bs[0][akq + 3][arow] = rb.w;
    __syncthreads();

    int buf = 0;
    for (int kt = 0; kt < KDIM; kt += BK) {
        const bool more = (kt + BK) < KDIM;
        if (more) {
            ra = *(const float4*)(Ag + kt + BK);
            rb = *(const float4*)(Bg + kt + BK);
        }
        #pragma unroll
        for (int k = 0; k < BK; k++) {
            float4 a0 = *(const float4*)&As[buf][k][tp * 4];
            float4 a1 = *(const float4*)&As[buf][k][tp * 4 + 64];
            float4 b0 = *(const float4*)&Bs[buf][k][tm * 4];
            float4 b1 = *(const float4*)&Bs[buf][k][tm * 4 + 64];
            float av[8] = {a0.x, a0.y, a0.z, a0.w, a1.x, a1.y, a1.z, a1.w};
            float bv[8] = {b0.x, b0.y, b0.z, b0.w, b1.x, b1.y, b1.z, b1.w};
            #pragma unroll
            for (int i = 0; i < 8; i++)
                #pragma unroll
                for (int j = 0; j < 8; j++)
                    acc[i][j] += av[i] * bv[j];
        }
        if (more) {
            const int nb = buf ^ 1;
            As[nb][akq + 0][arow] = ra.x; As[nb][akq + 1][arow] = ra.y;
            As[nb][akq + 2][arow] = ra.z; As[nb][akq + 3][arow] = ra.w;
            Bs[nb][akq + 0][arow] = rb.x; Bs[nb][akq + 1][arow] = rb.y;
            Bs[nb][akq + 2][arow] = rb.z; Bs[nb][akq + 3][arow] = rb.w;
        }
        __syncthreads();
        buf ^= 1;
    }

    // ---- epilogue ----
    int pidx[8], midx[8];
    #pragma unroll
    for (int i = 0; i < 4; i++) { pidx[i] = tp * 4 + i; pidx[i + 4] = 64 + tp * 4 + i; }
    #pragma unroll
    for (int j = 0; j < 4; j++) { midx[j] = tm * 4 + j; midx[j + 4] = 64 + tm * 4 + j; }

    float inva[8], invb[8], lb[8];
    #pragma unroll
    for (int i = 0; i < 8; i++) inva[i] = g_inv_test[prow0 + pidx[i]];
    #pragma unroll
    for (int j = 0; j < 8; j++) invb[j] = g_inv_train[mcol0 + midx[j]];
    #pragma unroll
    for (int j = 0; j < 8; j++) lb[j] = labf[midx[j]];

    #pragma unroll
    for (int i = 0; i < 8; i++) {
        float gt = 0.f, s1 = 0.f;
        #pragma unroll
        for (int j = 0; j < 8; j++) {
            float s  = acc[i][j] * inva[i] * invb[j];
            float d2 = fmaxf(2.f - 2.f * s, 0.f);
            float g  = __expf(-2.f * sqrtf(d2));
            gt += g;
            s1 += g * lb[j];
        }
        float s0 = gt - s1;
        #pragma unroll
        for (int off = 8; off; off >>= 1) {
            s0 += __shfl_down_sync(0xFFFFFFFFu, s0, off, 16);
            s1 += __shfl_down_sync(0xFFFFFFFFu, s1, off, 16);
        }
        if (tm == 0) {
            atomicAdd(&g_S[2 * (prow0 + pidx[i]) + 0], s0);
            atomicAdd(&g_S[2 * (prow0 + pidx[i]) + 1], s1);
        }
    }
}

// ---------------------------------------------------------------------------
// Finalize: prob = S / rowsum, results = argmax (ties -> class 0, like jnp).
// Output layout branched on out_size: 12288 => [results(4096) | prob(8192)].
// ---------------------------------------------------------------------------
__global__ void finalize_kernel(float* __restrict__ out, int out_size) {
    int p = blockIdx.x * blockDim.x + threadIdx.x;
    if (p >= NTEST) return;
    float s0 = g_S[2 * p], s1 = g_S[2 * p + 1];
    float p0 = s0 / (s0 + s1);
    float p1 = s1 / (s0 + s1);
    float res = (s1 > s0) ? 1.f : 0.f;
    if (out_size >= NTEST * 3) {
        out[p] = res;
        out[NTEST + 2 * p]     = p0;
        out[NTEST + 2 * p + 1] = p1;
    } else if (out_size == NTEST * 2) {
        out[2 * p]     = p0;
        out[2 * p + 1] = p1;
    } else {
        if (p < out_size) out[p] = res;
    }
}

// ---------------------------------------------------------------------------
extern "C" void kernel_launch(void* const* d_in, const int* in_sizes, int n_in,
                              void* d_out, int out_size) {
    // Identify inputs by element count (robust to metadata ordering).
    const float* train = nullptr;
    const float* test  = nullptr;
    const int*   label = nullptr;
    for (int i = 0; i < n_in; i++) {
        if (in_sizes[i] == NTRAIN * KDIM)      train = (const float*)d_in[i];
        else if (in_sizes[i] == NTEST * KDIM)  test  = (const float*)d_in[i];
        else if (in_sizes[i] == NTRAIN)        label = (const int*)d_in[i];
    }

    label_kernel<<<1, 1024>>>(label);
    norm_kernel<<<NTEST + NTRAIN, 128>>>(test, train);
    zero_kernel<<<(NTEST * 2 + 255) / 256, 256>>>();

    dim3 grid(NTRAIN / BN, NTEST / BM);
    pnn_gemm<<<grid, 256>>>(test, train);

    finalize_kernel<<<(NTEST + 255) / 256, 256>>>((float*)d_out, out_size);
}

// round 5
// speedup vs baseline: 2.3226x; 2.3226x over previous
#include <cuda_runtime.h>
#include <cuda_bf16.h>
#include <cstdint>
#include <math.h>

#define NTEST  4096
#define NTRAIN 8192
#define KDIM   1024

#define BM 128          // test rows per CTA
#define BN 256          // train rows per CTA
#define BK 64           // bf16 elements per chunk
#define NCHUNK 48       // 3 segments (hi*hi, hi*lo, lo*hi) x 16 chunks of 64

#define ST_A 0
#define ST_B 16384                 // A stage: 128 rows * 128B
#define STAGE 49152                // + B stage: 256 rows * 128B
#define SMEM_DYN (2 * STAGE + 1024)

#define SW(o) ((o) ^ (((o) >> 3) & 0x70))

__device__ __nv_bfloat16 g_Ahi[NTEST  * KDIM];
__device__ __nv_bfloat16 g_Alo[NTEST  * KDIM];
__device__ __nv_bfloat16 g_Bhi[NTRAIN * KDIM];
__device__ __nv_bfloat16 g_Blo[NTRAIN * KDIM];
__device__ float g_labf[NTRAIN];
__device__ float g_S[NTEST * 2];

// ---------------------------------------------------------------------------
__device__ __forceinline__ uint32_t smem_u32(const void* p) {
    uint32_t a;
    asm("{ .reg .u64 t; cvta.to.shared.u64 t, %1; cvt.u32.u64 %0, t; }" : "=r"(a) : "l"(p));
    return a;
}
__device__ __forceinline__ void cp16(uint32_t dst, const void* src) {
    asm volatile("cp.async.cg.shared.global [%0], [%1], 16;" :: "r"(dst), "l"(src));
}
#define CP_COMMIT() asm volatile("cp.async.commit_group;" ::: "memory")
#define CP_WAIT1()  asm volatile("cp.async.wait_group 1;" ::: "memory")

__device__ __forceinline__ void ldsm4(uint32_t& r0, uint32_t& r1, uint32_t& r2,
                                      uint32_t& r3, uint32_t a) {
    asm volatile("ldmatrix.sync.aligned.m8n8.x4.shared.b16 {%0,%1,%2,%3}, [%4];"
                 : "=r"(r0), "=r"(r1), "=r"(r2), "=r"(r3) : "r"(a));
}
__device__ __forceinline__ void mma16816(float* c, const uint32_t* a, const uint32_t* b) {
    asm volatile(
        "mma.sync.aligned.m16n8k16.row.col.f32.bf16.bf16.f32 "
        "{%0,%1,%2,%3}, {%4,%5,%6,%7}, {%8,%9}, {%0,%1,%2,%3};"
        : "+f"(c[0]), "+f"(c[1]), "+f"(c[2]), "+f"(c[3])
        : "r"(a[0]), "r"(a[1]), "r"(a[2]), "r"(a[3]), "r"(b[0]), "r"(b[1]));
}

// ---------------------------------------------------------------------------
// Label prep: detect int64 vs int32 storage, convert to float 0/1.
// ---------------------------------------------------------------------------
__global__ void label_kernel(const int* __restrict__ l32) {
    __shared__ int is64;
    if (threadIdx.x == 0) is64 = 1;
    __syncthreads();
    for (int i = threadIdx.x; i < NTRAIN / 2; i += blockDim.x)
        if (l32[2 * i + 1] != 0) is64 = 0;
    __syncthreads();
    const bool b64 = (is64 != 0);
    for (int i = threadIdx.x; i < NTRAIN; i += blockDim.x)
        g_labf[i] = (float)(b64 ? l32[2 * i] : l32[i]);
}

// ---------------------------------------------------------------------------
// Prep: per-row L2-normalize fp32, split into bf16 hi/lo.
// ---------------------------------------------------------------------------
__global__ __launch_bounds__(256)
void prep_kernel(const float* __restrict__ test, const float* __restrict__ train) {
    const int row = blockIdx.x;
    const float* src;
    __nv_bfloat16 *hi, *lo;
    if (row < NTEST) {
        src = test + (size_t)row * KDIM;
        hi = g_Ahi + (size_t)row * KDIM;
        lo = g_Alo + (size_t)row * KDIM;
    } else {
        int r = row - NTEST;
        src = train + (size_t)r * KDIM;
        hi = g_Bhi + (size_t)r * KDIM;
        lo = g_Blo + (size_t)r * KDIM;
    }
    const int tid = threadIdx.x;
    float4 v = ((const float4*)src)[tid];
    float s = v.x * v.x + v.y * v.y + v.z * v.z + v.w * v.w;
    #pragma unroll
    for (int off = 16; off; off >>= 1) s += __shfl_down_sync(0xFFFFFFFFu, s, off);
    __shared__ float red[8];
    __shared__ float s_inv;
    if ((tid & 31) == 0) red[tid >> 5] = s;
    __syncthreads();
    if (tid == 0) {
        float t = 0.f;
        #pragma unroll
        for (int i = 0; i < 8; i++) t += red[i];
        s_inv = rsqrtf(t);
    }
    __syncthreads();
    const float inv = s_inv;
    float x[4] = {v.x * inv, v.y * inv, v.z * inv, v.w * inv};
    __nv_bfloat16 h[4], l[4];
    #pragma unroll
    for (int i = 0; i < 4; i++) {
        h[i] = __float2bfloat16(x[i]);
        l[i] = __float2bfloat16(x[i] - __bfloat162float(h[i]));
    }
    ((uint2*)hi)[tid] = *(uint2*)h;
    ((uint2*)lo)[tid] = *(uint2*)l;
}

__global__ void zero_kernel() {
    int i = blockIdx.x * blockDim.x + threadIdx.x;
    if (i < NTEST * 2) g_S[i] = 0.f;
}

// ---------------------------------------------------------------------------
// stage loader: chunk c (0..47): seg = c/16 selects hi/lo operands
// ---------------------------------------------------------------------------
__device__ __forceinline__ void load_stage(uint32_t sb, int c, int prow0,
                                           int mcol0, int tid) {
    const __nv_bfloat16* Ag = (c < 32) ? g_Ahi : g_Alo;
    const __nv_bfloat16* Bg = (c < 16) ? g_Bhi : ((c < 32) ? g_Blo : g_Bhi);
    const int k0 = (c & 15) * BK;
    #pragma unroll
    for (int i = tid; i < 3072; i += 512) {
        const __nv_bfloat16* g;
        uint32_t base;
        int row, ch;
        if (i < 1024) {
            row = i >> 3; ch = i & 7;
            g = Ag + (size_t)(prow0 + row) * KDIM + k0 + ch * 8;
            base = sb + ST_A;
        } else {
            int j = i - 1024;
            row = j >> 3; ch = j & 7;
            g = Bg + (size_t)(mcol0 + row) * KDIM + k0 + ch * 8;
            base = sb + ST_B;
        }
        uint32_t off = row * 128 + ch * 16;
        cp16(base + SW(off), g);
    }
    CP_COMMIT();
}

// ---------------------------------------------------------------------------
// Main: bf16 mma.sync hi/lo split GEMM (128x256) + fused PNN epilogue
// ---------------------------------------------------------------------------
__global__ __launch_bounds__(512, 1)
void pnn_mma(int dummy) {
    extern __shared__ char dsm[];
    const int tid = threadIdx.x, lane = tid & 31, wid = tid >> 5;
    const int warp_m = wid >> 3, warp_n = wid & 7;   // 2 x 8 warp grid
    const int prow0 = blockIdx.y * BM;
    const int mcol0 = blockIdx.x * BN;

    uint32_t sb0 = (smem_u32(dsm) + 1023u) & ~1023u;
    uint32_t st[2] = {sb0, sb0 + STAGE};

    float acc[4][4][4];
    #pragma unroll
    for (int mt = 0; mt < 4; mt++)
        #pragma unroll
        for (int nt = 0; nt < 4; nt++)
            #pragma unroll
            for (int k = 0; k < 4; k++) acc[mt][nt][k] = 0.f;

    load_stage(st[0], 0, prow0, mcol0, tid);
    load_stage(st[1], 1, prow0, mcol0, tid);

    for (int c = 0; c < NCHUNK; c++) {
        CP_WAIT1();
        __syncthreads();
        const uint32_t sA = st[c & 1] + ST_A;
        const uint32_t sB = st[c & 1] + ST_B;

        #pragma unroll
        for (int s = 0; s < 4; s++) {
            uint32_t a[4][4], b[4][2];
            #pragma unroll
            for (int mt = 0; mt < 4; mt++) {
                int row = warp_m * 64 + mt * 16 + (lane & 15);
                int ch  = 2 * s + (lane >> 4);
                uint32_t off = row * 128 + ch * 16;
                ldsm4(a[mt][0], a[mt][1], a[mt][2], a[mt][3], sA + SW(off));
            }
            #pragma unroll
            for (int bt = 0; bt < 2; bt++) {
                int row = warp_n * 32 + bt * 16 + (lane & 7) + ((lane >> 4) << 3);
                int ch  = 2 * s + ((lane >> 3) & 1);
                uint32_t off = row * 128 + ch * 16;
                ldsm4(b[2 * bt][0], b[2 * bt][1], b[2 * bt + 1][0], b[2 * bt + 1][1],
                      sB + SW(off));
            }
            #pragma unroll
            for (int mt = 0; mt < 4; mt++)
                #pragma unroll
                for (int nt = 0; nt < 4; nt++)
                    mma16816(acc[mt][nt], a[mt], b[nt]);
        }
        __syncthreads();
        if (c + 2 < NCHUNK) load_stage(st[c & 1], c + 2, prow0, mcol0, tid);
        else                CP_COMMIT();   // keep wait_group bookkeeping aligned
    }

    // ---- epilogue: smem now reusable ----
    float* labf_s = (float*)dsm;              // 256 labels
    float* sS     = (float*)(dsm + 2048);     // 128 rows x 2 classes
    if (tid < 256) labf_s[tid] = g_labf[mcol0 + tid];
    if (tid >= 256 && tid < 512) sS[tid - 256] = 0.f;
    __syncthreads();

    #pragma unroll
    for (int mt = 0; mt < 4; mt++) {
        float r0s0 = 0.f, r0s1 = 0.f, r1s0 = 0.f, r1s1 = 0.f;
        #pragma unroll
        for (int nt = 0; nt < 4; nt++) {
            #pragma unroll
            for (int k = 0; k < 4; k++) {
                int cn = warp_n * 32 + nt * 8 + 2 * (lane & 3) + (k & 1);
                float s  = acc[mt][nt][k];
                float d2 = fmaxf(2.f - 2.f * s, 0.f);
                float sq;
                asm("sqrt.approx.f32 %0, %1;" : "=f"(sq) : "f"(d2));
                float g  = __expf(-2.f * sq);
                float lb = labf_s[cn];
                if (k < 2) { r0s0 += g; r0s1 += g * lb; }
                else       { r1s0 += g; r1s1 += g * lb; }
            }
        }
        r0s0 -= r0s1; r1s0 -= r1s1;
        #pragma unroll
        for (int off = 1; off < 4; off <<= 1) {
            r0s0 += __shfl_xor_sync(0xFFFFFFFFu, r0s0, off);
            r0s1 += __shfl_xor_sync(0xFFFFFFFFu, r0s1, off);
            r1s0 += __shfl_xor_sync(0xFFFFFFFFu, r1s0, off);
            r1s1 += __shfl_xor_sync(0xFFFFFFFFu, r1s1, off);
        }
        if ((lane & 3) == 0) {
            int rl = warp_m * 64 + mt * 16 + (lane >> 2);
            atomicAdd(&sS[2 * rl + 0], r0s0);
            atomicAdd(&sS[2 * rl + 1], r0s1);
            atomicAdd(&sS[2 * (rl + 8) + 0], r1s0);
            atomicAdd(&sS[2 * (rl + 8) + 1], r1s1);
        }
    }
    __syncthreads();
    if (tid < 256) atomicAdd(&g_S[2 * prow0 + tid], sS[tid]);
}

// ---------------------------------------------------------------------------
__global__ void finalize_kernel(float* __restrict__ out, int out_size) {
    int p = blockIdx.x * blockDim.x + threadIdx.x;
    if (p >= NTEST) return;
    float s0 = g_S[2 * p], s1 = g_S[2 * p + 1];
    float p0 = s0 / (s0 + s1);
    float p1 = s1 / (s0 + s1);
    float res = (s1 > s0) ? 1.f : 0.f;
    if (out_size >= NTEST * 3) {
        out[p] = res;
        out[NTEST + 2 * p]     = p0;
        out[NTEST + 2 * p + 1] = p1;
    } else if (out_size == NTEST * 2) {
        out[2 * p]     = p0;
        out[2 * p + 1] = p1;
    } else {
        if (p < out_size) out[p] = res;
    }
}

// ---------------------------------------------------------------------------
extern "C" void kernel_launch(void* const* d_in, const int* in_sizes, int n_in,
                              void* d_out, int out_size) {
    const float* train = nullptr;
    const float* test  = nullptr;
    const int*   label = nullptr;
    for (int i = 0; i < n_in; i++) {
        if (in_sizes[i] == NTRAIN * KDIM)      train = (const float*)d_in[i];
        else if (in_sizes[i] == NTEST * KDIM)  test  = (const float*)d_in[i];
        else if (in_sizes[i] == NTRAIN)        label = (const int*)d_in[i];
    }

    cudaFuncSetAttribute(pnn_mma, cudaFuncAttributeMaxDynamicSharedMemorySize, SMEM_DYN);

    label_kernel<<<1, 1024>>>(label);
    prep_kernel<<<NTEST + NTRAIN, 256>>>(test, train);
    zero_kernel<<<(NTEST * 2 + 255) / 256, 256>>>();

    dim3 grid(NTRAIN / BN, NTEST / BM);   // (32, 32)
    pnn_mma<<<grid, 512, SMEM_DYN>>>(0);

    finalize_kernel<<<(NTEST + 255) / 256, 256>>>((float*)d_out, out_size);
}

// round 6
// speedup vs baseline: 2.3309x; 1.0035x over previous
#include <cuda_runtime.h>
#include <cuda_bf16.h>
#include <cstdint>
#include <math.h>

#define NTEST  4096
#define NTRAIN 8192
#define KDIM   1024

#define BM 128          // test rows per CTA
#define BN 256          // train rows per CTA
#define BK 64           // bf16 elements per chunk
#define NCHUNK 48       // 3 segments (hi*hi, hi*lo, lo*hi) x 16 chunks of 64

#define ST_A 0
#define ST_B 16384                 // A stage: 128 rows * 128B
#define STAGE 49152                // + B stage: 256 rows * 128B = 48KB
#define NSTAGE 3
#define SMEM_DYN (NSTAGE * STAGE + 1024)

#define SW(o) ((o) ^ (((o) >> 3) & 0x70))

__device__ __nv_bfloat16 g_Ahi[NTEST  * KDIM];
__device__ __nv_bfloat16 g_Alo[NTEST  * KDIM];
__device__ __nv_bfloat16 g_Bhi[NTRAIN * KDIM];
__device__ __nv_bfloat16 g_Blo[NTRAIN * KDIM];
__device__ float g_labf[NTRAIN];
__device__ float g_S[NTEST * 2];

// ---------------------------------------------------------------------------
__device__ __forceinline__ uint32_t smem_u32(const void* p) {
    uint32_t a;
    asm("{ .reg .u64 t; cvta.to.shared.u64 t, %1; cvt.u32.u64 %0, t; }" : "=r"(a) : "l"(p));
    return a;
}
__device__ __forceinline__ void cp16(uint32_t dst, const void* src) {
    asm volatile("cp.async.cg.shared.global [%0], [%1], 16;" :: "r"(dst), "l"(src));
}
#define CP_COMMIT() asm volatile("cp.async.commit_group;" ::: "memory")
#define CP_WAIT1()  asm volatile("cp.async.wait_group 1;" ::: "memory")

__device__ __forceinline__ void ldsm4(uint32_t& r0, uint32_t& r1, uint32_t& r2,
                                      uint32_t& r3, uint32_t a) {
    asm volatile("ldmatrix.sync.aligned.m8n8.x4.shared.b16 {%0,%1,%2,%3}, [%4];"
                 : "=r"(r0), "=r"(r1), "=r"(r2), "=r"(r3) : "r"(a));
}
__device__ __forceinline__ void mma16816(float* c, const uint32_t* a, const uint32_t* b) {
    asm volatile(
        "mma.sync.aligned.m16n8k16.row.col.f32.bf16.bf16.f32 "
        "{%0,%1,%2,%3}, {%4,%5,%6,%7}, {%8,%9}, {%0,%1,%2,%3};"
        : "+f"(c[0]), "+f"(c[1]), "+f"(c[2]), "+f"(c[3])
        : "r"(a[0]), "r"(a[1]), "r"(a[2]), "r"(a[3]), "r"(b[0]), "r"(b[1]));
}

// ---------------------------------------------------------------------------
// Label prep: detect int64 vs int32 storage, convert to float 0/1.
// ---------------------------------------------------------------------------
__global__ void label_kernel(const int* __restrict__ l32) {
    __shared__ int is64;
    if (threadIdx.x == 0) is64 = 1;
    __syncthreads();
    for (int i = threadIdx.x; i < NTRAIN / 2; i += blockDim.x)
        if (l32[2 * i + 1] != 0) is64 = 0;
    __syncthreads();
    const bool b64 = (is64 != 0);
    for (int i = threadIdx.x; i < NTRAIN; i += blockDim.x)
        g_labf[i] = (float)(b64 ? l32[2 * i] : l32[i]);
}

// ---------------------------------------------------------------------------
// Prep: per-row L2-normalize fp32, split into bf16 hi/lo.
// ---------------------------------------------------------------------------
__global__ __launch_bounds__(256)
void prep_kernel(const float* __restrict__ test, const float* __restrict__ train) {
    const int row = blockIdx.x;
    const float* src;
    __nv_bfloat16 *hi, *lo;
    if (row < NTEST) {
        src = test + (size_t)row * KDIM;
        hi = g_Ahi + (size_t)row * KDIM;
        lo = g_Alo + (size_t)row * KDIM;
    } else {
        int r = row - NTEST;
        src = train + (size_t)r * KDIM;
        hi = g_Bhi + (size_t)r * KDIM;
        lo = g_Blo + (size_t)r * KDIM;
    }
    const int tid = threadIdx.x;
    float4 v = ((const float4*)src)[tid];
    float s = v.x * v.x + v.y * v.y + v.z * v.z + v.w * v.w;
    #pragma unroll
    for (int off = 16; off; off >>= 1) s += __shfl_down_sync(0xFFFFFFFFu, s, off);
    __shared__ float red[8];
    __shared__ float s_inv;
    if ((tid & 31) == 0) red[tid >> 5] = s;
    __syncthreads();
    if (tid == 0) {
        float t = 0.f;
        #pragma unroll
        for (int i = 0; i < 8; i++) t += red[i];
        s_inv = rsqrtf(t);
    }
    __syncthreads();
    const float inv = s_inv;
    float x[4] = {v.x * inv, v.y * inv, v.z * inv, v.w * inv};
    __nv_bfloat16 h[4], l[4];
    #pragma unroll
    for (int i = 0; i < 4; i++) {
        h[i] = __float2bfloat16(x[i]);
        l[i] = __float2bfloat16(x[i] - __bfloat162float(h[i]));
    }
    ((uint2*)hi)[tid] = *(uint2*)h;
    ((uint2*)lo)[tid] = *(uint2*)l;
}

__global__ void zero_kernel() {
    int i = blockIdx.x * blockDim.x + threadIdx.x;
    if (i < NTEST * 2) g_S[i] = 0.f;
}

// ---------------------------------------------------------------------------
// stage loader: chunk c (0..47): seg = c/16 selects hi/lo operands
// ---------------------------------------------------------------------------
__device__ __forceinline__ void load_stage(uint32_t sb, int c, int prow0,
                                           int mcol0, int tid) {
    const __nv_bfloat16* Ag = (c < 32) ? g_Ahi : g_Alo;
    const __nv_bfloat16* Bg = (c < 16) ? g_Bhi : ((c < 32) ? g_Blo : g_Bhi);
    const int k0 = (c & 15) * BK;
    #pragma unroll
    for (int i = tid; i < 3072; i += 512) {
        const __nv_bfloat16* g;
        uint32_t base;
        int row, ch;
        if (i < 1024) {
            row = i >> 3; ch = i & 7;
            g = Ag + (size_t)(prow0 + row) * KDIM + k0 + ch * 8;
            base = sb + ST_A;
        } else {
            int j = i - 1024;
            row = j >> 3; ch = j & 7;
            g = Bg + (size_t)(mcol0 + row) * KDIM + k0 + ch * 8;
            base = sb + ST_B;
        }
        uint32_t off = row * 128 + ch * 16;
        cp16(base + SW(off), g);
    }
    CP_COMMIT();
}

// ---------------------------------------------------------------------------
// Main: bf16 mma.sync hi/lo split GEMM (128x256) + fused PNN epilogue.
// 3-stage cp.async ring, ONE barrier per chunk, loads issued before compute.
// ---------------------------------------------------------------------------
__global__ __launch_bounds__(512, 1)
void pnn_mma(int dummy) {
    extern __shared__ char dsm[];
    const int tid = threadIdx.x, lane = tid & 31, wid = tid >> 5;
    const int warp_m = wid >> 3, warp_n = wid & 7;   // 2 x 8 warp grid
    const int prow0 = blockIdx.y * BM;
    const int mcol0 = blockIdx.x * BN;

    uint32_t sb0 = (smem_u32(dsm) + 1023u) & ~1023u;
    uint32_t st[NSTAGE] = {sb0, sb0 + STAGE, sb0 + 2 * STAGE};

    float acc[4][4][4];
    #pragma unroll
    for (int mt = 0; mt < 4; mt++)
        #pragma unroll
        for (int nt = 0; nt < 4; nt++)
            #pragma unroll
            for (int k = 0; k < 4; k++) acc[mt][nt][k] = 0.f;

    // prologue: chunks 0,1 in flight
    load_stage(st[0], 0, prow0, mcol0, tid);
    load_stage(st[1], 1, prow0, mcol0, tid);

    int cs = 0;                          // stage index = c % 3 (no modulo)
    for (int c = 0; c < NCHUNK; c++) {
        CP_WAIT1();                      // chunk c's data complete (this thread)
        __syncthreads();                 // visibility + stage (c-1)%3 fully consumed

        // refill stage (c+2)%3 (consumed at chunk c-1) BEFORE compute
        int ls = cs + 2; if (ls >= NSTAGE) ls -= NSTAGE;
        if (c + 2 < NCHUNK) load_stage(st[ls], c + 2, prow0, mcol0, tid);

        const uint32_t sA = st[cs] + ST_A;
        const uint32_t sB = st[cs] + ST_B;

        #pragma unroll
        for (int s = 0; s < 4; s++) {
            uint32_t a[4][4], b[4][2];
            #pragma unroll
            for (int mt = 0; mt < 4; mt++) {
                int row = warp_m * 64 + mt * 16 + (lane & 15);
                int ch  = 2 * s + (lane >> 4);
                uint32_t off = row * 128 + ch * 16;
                ldsm4(a[mt][0], a[mt][1], a[mt][2], a[mt][3], sA + SW(off));
            }
            #pragma unroll
            for (int bt = 0; bt < 2; bt++) {
                int row = warp_n * 32 + bt * 16 + (lane & 7) + ((lane >> 4) << 3);
                int ch  = 2 * s + ((lane >> 3) & 1);
                uint32_t off = row * 128 + ch * 16;
                ldsm4(b[2 * bt][0], b[2 * bt][1], b[2 * bt + 1][0], b[2 * bt + 1][1],
                      sB + SW(off));
            }
            #pragma unroll
            for (int mt = 0; mt < 4; mt++)
                #pragma unroll
                for (int nt = 0; nt < 4; nt++)
                    mma16816(acc[mt][nt], a[mt], b[nt]);
        }

        if (++cs >= NSTAGE) cs = 0;
    }
    __syncthreads();   // all warps done with smem before epilogue reuse

    // ---- epilogue: smem now reusable ----
    float* labf_s = (float*)dsm;              // 256 labels
    float* sS     = (float*)(dsm + 2048);     // 128 rows x 2 classes
    if (tid < 256) labf_s[tid] = g_labf[mcol0 + tid];
    if (tid >= 256 && tid < 512) sS[tid - 256] = 0.f;
    __syncthreads();

    #pragma unroll
    for (int mt = 0; mt < 4; mt++) {
        float r0s0 = 0.f, r0s1 = 0.f, r1s0 = 0.f, r1s1 = 0.f;
        #pragma unroll
        for (int nt = 0; nt < 4; nt++) {
            #pragma unroll
            for (int k = 0; k < 4; k++) {
                int cn = warp_n * 32 + nt * 8 + 2 * (lane & 3) + (k & 1);
                float s  = acc[mt][nt][k];
                float d2 = fmaxf(2.f - 2.f * s, 0.f);
                float sq;
                asm("sqrt.approx.f32 %0, %1;" : "=f"(sq) : "f"(d2));
                float g  = __expf(-2.f * sq);
                float lb = labf_s[cn];
                if (k < 2) { r0s0 += g; r0s1 += g * lb; }
                else       { r1s0 += g; r1s1 += g * lb; }
            }
        }
        r0s0 -= r0s1; r1s0 -= r1s1;
        #pragma unroll
        for (int off = 1; off < 4; off <<= 1) {
            r0s0 += __shfl_xor_sync(0xFFFFFFFFu, r0s0, off);
            r0s1 += __shfl_xor_sync(0xFFFFFFFFu, r0s1, off);
            r1s0 += __shfl_xor_sync(0xFFFFFFFFu, r1s0, off);
            r1s1 += __shfl_xor_sync(0xFFFFFFFFu, r1s1, off);
        }
        if ((lane & 3) == 0) {
            int rl = warp_m * 64 + mt * 16 + (lane >> 2);
            atomicAdd(&sS[2 * rl + 0], r0s0);
            atomicAdd(&sS[2 * rl + 1], r0s1);
            atomicAdd(&sS[2 * (rl + 8) + 0], r1s0);
            atomicAdd(&sS[2 * (rl + 8) + 1], r1s1);
        }
    }
    __syncthreads();
    if (tid < 256) atomicAdd(&g_S[2 * prow0 + tid], sS[tid]);
}

// ---------------------------------------------------------------------------
__global__ void finalize_kernel(float* __restrict__ out, int out_size) {
    int p = blockIdx.x * blockDim.x + threadIdx.x;
    if (p >= NTEST) return;
    float s0 = g_S[2 * p], s1 = g_S[2 * p + 1];
    float p0 = s0 / (s0 + s1);
    float p1 = s1 / (s0 + s1);
    float res = (s1 > s0) ? 1.f : 0.f;
    if (out_size >= NTEST * 3) {
        out[p] = res;
        out[NTEST + 2 * p]     = p0;
        out[NTEST + 2 * p + 1] = p1;
    } else if (out_size == NTEST * 2) {
        out[2 * p]     = p0;
        out[2 * p + 1] = p1;
    } else {
        if (p < out_size) out[p] = res;
    }
}

// ---------------------------------------------------------------------------
extern "C" void kernel_launch(void* const* d_in, const int* in_sizes, int n_in,
                              void* d_out, int out_size) {
    const float* train = nullptr;
    const float* test  = nullptr;
    const int*   label = nullptr;
    for (int i = 0; i < n_in; i++) {
        if (in_sizes[i] == NTRAIN * KDIM)      train = (const float*)d_in[i];
        else if (in_sizes[i] == NTEST * KDIM)  test  = (const float*)d_in[i];
        else if (in_sizes[i] == NTRAIN)        label = (const int*)d_in[i];
    }

    cudaFuncSetAttribute(pnn_mma, cudaFuncAttributeMaxDynamicSharedMemorySize, SMEM_DYN);

    label_kernel<<<1, 1024>>>(label);
    prep_kernel<<<NTEST + NTRAIN, 256>>>(test, train);
    zero_kernel<<<(NTEST * 2 + 255) / 256, 256>>>();

    dim3 grid(NTRAIN / BN, NTEST / BM);   // (32, 32)
    pnn_mma<<<grid, 512, SMEM_DYN>>>(0);

    finalize_kernel<<<(NTEST + 255) / 256, 256>>>((float*)d_out, out_size);
}